// round 7
// baseline (speedup 1.0000x reference)
#include <cuda_runtime.h>
#include <cstdint>

// LinearKoopmanLayer: per-(b,f) complex rotation of channel pair (2f, 2f+1).
// x: (B=256, 2F=128, T=1024) fp32, out same shape.
//   a = amp[f]^dt[b];  c = a*cos(freq[f]*dt[b]);  s = a*sin(freq[f]*dt[b])
//   out[b,2f,t]   = c*x0 - s*x1
//   out[b,2f+1,t] = s*x0 + c*x1
//
// Key cache insight: x (128 MB) nearly fits GB300's ~126 MB L2, and graph
// replays re-read it — so default loads get cross-replay L2 hits (DRAM
// counter 5.95 TB/s vs 7.48 TB/s apparent in R4). Writes (128 MB, dead
// after the launch) thrash that residency. Fix: streaming stores (__stcs,
// evict-first) so output lines don't evict live x lines; loads stay DEFAULT
// (R5 showed evict-first LOADS destroy the reuse: 36->47 us).
//
// Shape: best-measured R4 config. 64 threads per (b,f) pair, 4 float4 per
// row per thread (MLP=8, warp-coalesced), 4 pairs per 256-thread CTA.

#define B_DIM 256
#define F_DIM 64
#define T_DIM 1024
#define T_VEC (T_DIM / 4)      // 256 float4 per row
#define BF_PER_BLOCK 4

__global__ __launch_bounds__(256, 8)
void koopman_kernel(const float* __restrict__ x,
                    const float* __restrict__ delta_t,
                    const float* __restrict__ amplitudes,
                    const float* __restrict__ frequencies,
                    float* __restrict__ out) {
    const int bf = blockIdx.x * BF_PER_BLOCK + (threadIdx.x >> 6);  // b*64+f
    const int t0 = threadIdx.x & 63;
    const int b  = bf >> 6;
    const int f  = bf & 63;

    // Scalar loads first: they head the longest dep chain (LDG -> pow -> sincos).
    const float d   = __ldg(&delta_t[b]);
    const float amp = __ldg(&amplitudes[f]);
    const float frq = __ldg(&frequencies[f]);

    // rows 2f, 2f+1 of batch b -> global rows 2*bf, 2*bf+1 (contiguous 2 KB)
    const size_t base = (size_t)bf * (2 * T_DIM);
    const float4* __restrict__ x0 = reinterpret_cast<const float4*>(x + base);
    const float4* __restrict__ x1 = x0 + T_VEC;
    float4* __restrict__ o0 = reinterpret_cast<float4*>(out + base);
    float4* __restrict__ o1 = o0 + T_VEC;

    // Front-batch all 8 vector loads (MLP=8), DEFAULT cache policy
    // (preserves cross-replay L2 residency of x).
    float4 v0[4], v1[4];
#pragma unroll
    for (int i = 0; i < 4; i++) v0[i] = x0[t0 + 64 * i];
#pragma unroll
    for (int i = 0; i < 4; i++) v1[i] = x1[t0 + 64 * i];

    // Coefficient: once per thread, fast intrinsics (err << 1e-3 budget).
    const float a = __powf(amp, d);         // amp in [0.7,1.3], d in [0.5,2]
    float s, c;
    __sincosf(frq * d, &s, &c);             // ang in [0, 4*pi]
    c *= a;
    s *= a;

#pragma unroll
    for (int i = 0; i < 4; i++) {
        float4 r0, r1;
        r0.x = c * v0[i].x - s * v1[i].x;  r1.x = s * v0[i].x + c * v1[i].x;
        r0.y = c * v0[i].y - s * v1[i].y;  r1.y = s * v0[i].y + c * v1[i].y;
        r0.z = c * v0[i].z - s * v1[i].z;  r1.z = s * v0[i].z + c * v1[i].z;
        r0.w = c * v0[i].w - s * v1[i].w;  r1.w = s * v0[i].w + c * v1[i].w;
        // Streaming stores: evict-first so dead output lines don't evict x.
        __stcs(&o0[t0 + 64 * i], r0);
        __stcs(&o1[t0 + 64 * i], r1);
    }
}

extern "C" void kernel_launch(void* const* d_in, const int* in_sizes, int n_in,
                              void* d_out, int out_size) {
    const float* x           = (const float*)d_in[0];
    const float* delta_t     = (const float*)d_in[1];
    const float* amplitudes  = (const float*)d_in[2];
    const float* frequencies = (const float*)d_in[3];
    float* out = (float*)d_out;

    dim3 grid((B_DIM * F_DIM) / BF_PER_BLOCK);   // 4096 blocks
    dim3 block(256);
    koopman_kernel<<<grid, block>>>(x, delta_t, amplitudes, frequencies, out);
}

// round 8
// speedup vs baseline: 1.0028x; 1.0028x over previous
#include <cuda_runtime.h>
#include <cstdint>

// LinearKoopmanLayer: per-(b,f) complex rotation of channel pair (2f, 2f+1).
// x: (B=256, 2F=128, T=1024) fp32, out same shape.
//   a = amp[f]^dt[b];  c = a*cos(freq[f]*dt[b]);  s = a*sin(freq[f]*dt[b])
//   out[b,2f,t]   = c*x0 - s*x1
//   out[b,2f+1,t] = s*x0 + c*x1
//
// FINAL (pinned R4 config — measured optimum across 5 variants):
//   - default cache policy on loads AND stores (any .cs qualifier regresses:
//     ldcs+stcs 46.9us, stcs-only 37.5us, default 35.9us)
//   - 4096 CTAs x 256 threads beats 16384x256 (36.7) and 2048x512 (36.7)
//   - 268.4 MB L2 traffic / 35.9us = 7.48 TB/s = the path-independent
//     LTS cap (~6300 B/cyc @ NAT clock) -> structural floor, traffic
//     is irreducible (each byte touched exactly once).
//
// Layout: 64 threads per (b,f) pair, each thread 4 float4 per row at
// t0+{0,64,128,192} (warp-coalesced 128B), MLP_p1=8 front-batched loads.
// Coefficient (pow + sincos) once per thread via fast intrinsics, its MUFU
// latency hidden under the outstanding loads. rel_err 4e-7 << 1e-3 budget.

#define B_DIM 256
#define F_DIM 64
#define T_DIM 1024
#define T_VEC (T_DIM / 4)      // 256 float4 per row
#define BF_PER_BLOCK 4

__global__ __launch_bounds__(256, 8)
void koopman_kernel(const float* __restrict__ x,
                    const float* __restrict__ delta_t,
                    const float* __restrict__ amplitudes,
                    const float* __restrict__ frequencies,
                    float* __restrict__ out) {
    const int bf = blockIdx.x * BF_PER_BLOCK + (threadIdx.x >> 6);  // b*64+f
    const int t0 = threadIdx.x & 63;
    const int b  = bf >> 6;
    const int f  = bf & 63;

    // Scalar loads first: they head the longest dep chain (LDG -> pow -> sincos).
    const float d   = __ldg(&delta_t[b]);
    const float amp = __ldg(&amplitudes[f]);
    const float frq = __ldg(&frequencies[f]);

    // rows 2f, 2f+1 of batch b -> global rows 2*bf, 2*bf+1 (contiguous 2 KB)
    const size_t base = (size_t)bf * (2 * T_DIM);
    const float4* __restrict__ x0 = reinterpret_cast<const float4*>(x + base);
    const float4* __restrict__ x1 = x0 + T_VEC;
    float4* __restrict__ o0 = reinterpret_cast<float4*>(out + base);
    float4* __restrict__ o1 = o0 + T_VEC;

    // Front-batch all 8 vector loads (MLP=8), default cache policy.
    float4 v0[4], v1[4];
#pragma unroll
    for (int i = 0; i < 4; i++) v0[i] = x0[t0 + 64 * i];
#pragma unroll
    for (int i = 0; i < 4; i++) v1[i] = x1[t0 + 64 * i];

    // Coefficient: once per thread, fast intrinsics (err << 1e-3 budget).
    const float a = __powf(amp, d);         // amp in [0.7,1.3], d in [0.5,2]
    float s, c;
    __sincosf(frq * d, &s, &c);             // ang in [0, 4*pi]
    c *= a;
    s *= a;

#pragma unroll
    for (int i = 0; i < 4; i++) {
        float4 r0, r1;
        r0.x = c * v0[i].x - s * v1[i].x;  r1.x = s * v0[i].x + c * v1[i].x;
        r0.y = c * v0[i].y - s * v1[i].y;  r1.y = s * v0[i].y + c * v1[i].y;
        r0.z = c * v0[i].z - s * v1[i].z;  r1.z = s * v0[i].z + c * v1[i].z;
        r0.w = c * v0[i].w - s * v1[i].w;  r1.w = s * v0[i].w + c * v1[i].w;
        o0[t0 + 64 * i] = r0;
        o1[t0 + 64 * i] = r1;
    }
}

extern "C" void kernel_launch(void* const* d_in, const int* in_sizes, int n_in,
                              void* d_out, int out_size) {
    const float* x           = (const float*)d_in[0];
    const float* delta_t     = (const float*)d_in[1];
    const float* amplitudes  = (const float*)d_in[2];
    const float* frequencies = (const float*)d_in[3];
    float* out = (float*)d_out;

    dim3 grid((B_DIM * F_DIM) / BF_PER_BLOCK);   // 4096 blocks
    dim3 block(256);
    koopman_kernel<<<grid, block>>>(x, delta_t, amplitudes, frequencies, out);
}